// round 16
// baseline (speedup 1.0000x reference)
#include <cuda_runtime.h>
#include <cuda_bf16.h>
#include <math.h>
#include <stdint.h>

// Problem constants
#define BATCH 2
#define SEQ   2048
#define DIM   2048
#define NHEAD 16
#define HDIM  128
#define MTOT  (BATCH * SEQ)      // 4096 rows
#define ELEMS ((size_t)BATCH * SEQ * DIM)   // 8388608
#define WSZ   ((size_t)DIM * DIM)           // 4194304

// ---------------- scratch (no allocations allowed) ----------------
__device__ float g_Q[ELEMS];
__device__ float g_K[ELEMS];
__device__ __align__(16) __nv_bfloat16 g_ah[ELEMS];          // A hi (x, then attn-out)
__device__ __align__(16) __nv_bfloat16 g_al[ELEMS];          // A lo
__device__ __align__(16) __nv_bfloat16 g_bh[4 * WSZ];        // Wq,Wk,Wv,Wo hi
__device__ __align__(16) __nv_bfloat16 g_bl[4 * WSZ];        // Wq,Wk,Wv,Wo lo
__device__ __align__(16) __nv_bfloat16 g_qh[ELEMS];
__device__ __align__(16) __nv_bfloat16 g_ql[ELEMS];
__device__ __align__(16) __nv_bfloat16 g_kh[ELEMS];
__device__ __align__(16) __nv_bfloat16 g_kl[ELEMS];
__device__ __align__(16) __nv_bfloat16 g_vh[ELEMS];
__device__ __align__(16) __nv_bfloat16 g_vl[ELEMS];
__device__ double g_invfreq[64];

// ============================================================================
// mma.sync / ldmatrix / cp.async helpers (all legal at compute_103)
// ============================================================================
__device__ __forceinline__ uint32_t smem_u32(const void* p) {
    uint32_t a;
    asm("{ .reg .u64 t; cvta.to.shared.u64 t, %1; cvt.u32.u64 %0, t; }"
        : "=r"(a) : "l"(p));
    return a;
}

__device__ __forceinline__ void ldsm_x4(uint32_t (&r)[4], uint32_t addr) {
    asm volatile("ldmatrix.sync.aligned.m8n8.x4.shared.b16 {%0,%1,%2,%3}, [%4];"
                 : "=r"(r[0]), "=r"(r[1]), "=r"(r[2]), "=r"(r[3]) : "r"(addr));
}

__device__ __forceinline__ void ldsm_x4_t(uint32_t (&r)[4], uint32_t addr) {
    asm volatile("ldmatrix.sync.aligned.m8n8.x4.trans.shared.b16 {%0,%1,%2,%3}, [%4];"
                 : "=r"(r[0]), "=r"(r[1]), "=r"(r[2]), "=r"(r[3]) : "r"(addr));
}

__device__ __forceinline__ void mma_bf16(float (&c)[4], const uint32_t (&a)[4],
                                         uint32_t b0, uint32_t b1) {
    asm volatile(
        "mma.sync.aligned.m16n8k16.row.col.f32.bf16.bf16.f32 "
        "{%0,%1,%2,%3}, {%4,%5,%6,%7}, {%8,%9}, {%0,%1,%2,%3};"
        : "+f"(c[0]), "+f"(c[1]), "+f"(c[2]), "+f"(c[3])
        : "r"(a[0]), "r"(a[1]), "r"(a[2]), "r"(a[3]), "r"(b0), "r"(b1));
}

#define CP_ASYNC16(dst, src) \
    asm volatile("cp.async.ca.shared.global [%0], [%1], 16;" \
                 :: "r"(dst), "l"(src) : "memory")
#define CP_COMMIT() asm volatile("cp.async.commit_group;" ::: "memory")
#define CP_WAIT0()  asm volatile("cp.async.wait_group 0;" ::: "memory")
#define CP_WAIT1()  asm volatile("cp.async.wait_group 1;" ::: "memory")
#define CP_WAIT2()  asm volatile("cp.async.wait_group 2;" ::: "memory")

// hi/lo bf16 pair packing
__device__ __forceinline__ void split2pack(float a, float b, uint32_t& h, uint32_t& l) {
    __nv_bfloat16 ha = __float2bfloat16(a), hb = __float2bfloat16(b);
    __nv_bfloat162 th(ha, hb);
    h = *reinterpret_cast<uint32_t*>(&th);
    __nv_bfloat162 tl(__float2bfloat16(a - __bfloat162float(ha)),
                      __float2bfloat16(b - __bfloat162float(hb)));
    l = *reinterpret_cast<uint32_t*>(&tl);
}

// ============================================================================
// bf16x3 tensor-core GEMM (NT): C[m,n] = sum_k A[m,k]*B[n,k]
// CTA tile 128x128, 128 threads = 4 warps (2m x 2n), warp tile 64x64.
// 4-stage cp.async pipeline, 16 k-columns per stage (prefetch distance 3).
// smem row stride 48B (16B-aligned; 48r/16 mod 8 covers all 8 bank-groups ->
// conflict-free ldsm). 2 CTAs/SM. blockIdx.z selects weight slice + output:
//   z=0 -> fp32 C0, z=1 -> fp32 C1, z=2 -> bf16 hi/lo C2h/C2l.
// Per k16-step: 16 ldsm hoisted, then uninterrupted 48-mma burst.
// ============================================================================
#define G4_STR  48
#define G4_TILE (128 * G4_STR)            // 6144 B per tile
#define S_AH 0
#define S_AL (G4_TILE)
#define S_BH (2 * G4_TILE)
#define S_BL (3 * G4_TILE)
#define G4_STAGE (4 * G4_TILE)            // 24576 per stage
#define G_SMEM (4 * G4_STAGE)             // 98304 (2 CTAs/SM: 196KB <= 227KB)

__global__ __launch_bounds__(128, 2)
void gemm_mma(const __nv_bfloat16* __restrict__ Ah, const __nv_bfloat16* __restrict__ Al,
              const __nv_bfloat16* __restrict__ BhBase,
              const __nv_bfloat16* __restrict__ BlBase,
              float* __restrict__ C0, float* __restrict__ C1,
              __nv_bfloat16* __restrict__ C2h, __nv_bfloat16* __restrict__ C2l,
              int M, int N, int K)
{
    extern __shared__ __align__(16) char sm[];
    const uint32_t smb = smem_u32(sm);
    const int tid = threadIdx.x;
    const int wid = tid >> 5, lane = tid & 31;
    const int wm = wid & 1, wn = wid >> 1;            // 2 x 2 warp grid
    const int m0 = blockIdx.y * 128, n0 = blockIdx.x * 128;
    const int z = blockIdx.z;
    const __nv_bfloat16* Bh = BhBase + (size_t)z * WSZ;
    const __nv_bfloat16* Bl = BlBase + (size_t)z * WSZ;

    // ldmatrix lane-address components (row stride 48B, k16 tiles)
    const uint32_t aoff = (uint32_t)(((lane & 7) + 8 * ((lane >> 3) & 1)) * G4_STR
                                     + 16 * (lane >> 4));
    const uint32_t boff = (uint32_t)(((lane & 7) + 8 * (lane >> 4)) * G4_STR
                                     + 16 * ((lane >> 3) & 1));

    // per-thread load coords: 2 chunks of 16B per row-half; rows 0..127
    const int lr = tid >> 1, lc = tid & 1;            // lr 0..63, lc 0..1

    auto load_stage = [&](int k16, int st) {
        uint32_t base = smb + (uint32_t)(st * G4_STAGE);
#pragma unroll
        for (int i = 0; i < 2; i++) {
            int r = lr + 64 * i;
            uint32_t so = (uint32_t)(r * G4_STR + lc * 16);
            size_t ga = (size_t)(m0 + r) * K + (size_t)k16 * 16 + lc * 8;
            size_t gb = (size_t)(n0 + r) * K + (size_t)k16 * 16 + lc * 8;
            CP_ASYNC16(base + S_AH + so, Ah + ga);
            CP_ASYNC16(base + S_AL + so, Al + ga);
            CP_ASYNC16(base + S_BH + so, Bh + gb);
            CP_ASYNC16(base + S_BL + so, Bl + gb);
        }
        CP_COMMIT();
    };

    float acc[4][8][4];
#pragma unroll
    for (int i = 0; i < 4; i++)
#pragma unroll
        for (int j = 0; j < 8; j++)
#pragma unroll
            for (int v = 0; v < 4; v++) acc[i][j][v] = 0.f;

    const int KB16 = K >> 4;   // 128 k16-steps
    load_stage(0, 0);
    load_stage(1, 1);
    load_stage(2, 2);

    for (int s = 0; s < KB16; s++) {
        // wait until stage s's group has landed (peeled tail depths)
        int rem = KB16 - 1 - s;
        if (rem >= 2)      { CP_WAIT2(); }
        else if (rem == 1) { CP_WAIT1(); }
        else               { CP_WAIT0(); }
        __syncthreads();   // all warps done with stage s-1 (its buffer = (s+3)&3)
        if (s + 3 < KB16) load_stage(s + 3, (s + 3) & 3);

        const uint32_t sb = smb + (uint32_t)((s & 3) * G4_STAGE);
        uint32_t ah_[4][4], al_[4][4], bhf[4][4], blf[4][4];
        // hoist ALL fragment loads (16 ldsm) ...
#pragma unroll
        for (int f = 0; f < 4; f++) {
            uint32_t ro = (uint32_t)((wm * 64 + 16 * f) * G4_STR);
            ldsm_x4(ah_[f], sb + S_AH + ro + aoff);
            ldsm_x4(al_[f], sb + S_AL + ro + aoff);
        }
#pragma unroll
        for (int j = 0; j < 4; j++) {
            uint32_t ro = (uint32_t)((wn * 64 + 16 * j) * G4_STR);
            ldsm_x4(bhf[j], sb + S_BH + ro + boff);
            ldsm_x4(blf[j], sb + S_BL + ro + boff);
        }
        // ... then one uninterrupted 48-mma burst (32 indep accumulators)
#pragma unroll
        for (int f = 0; f < 4; f++)
#pragma unroll
            for (int j = 0; j < 4; j++) {
                mma_bf16(acc[f][2 * j + 0], ah_[f], bhf[j][0], bhf[j][1]);
                mma_bf16(acc[f][2 * j + 1], ah_[f], bhf[j][2], bhf[j][3]);
            }
#pragma unroll
        for (int f = 0; f < 4; f++)
#pragma unroll
            for (int j = 0; j < 4; j++) {
                mma_bf16(acc[f][2 * j + 0], al_[f], bhf[j][0], bhf[j][1]);
                mma_bf16(acc[f][2 * j + 1], al_[f], bhf[j][2], bhf[j][3]);
            }
#pragma unroll
        for (int f = 0; f < 4; f++)
#pragma unroll
            for (int j = 0; j < 4; j++) {
                mma_bf16(acc[f][2 * j + 0], ah_[f], blf[j][0], blf[j][1]);
                mma_bf16(acc[f][2 * j + 1], ah_[f], blf[j][2], blf[j][3]);
            }
    }

    const int g = lane >> 2, cq = lane & 3;
    if (z == 2) {
#pragma unroll
        for (int f = 0; f < 4; f++)
#pragma unroll
            for (int j = 0; j < 8; j++) {
                int row = m0 + wm * 64 + 16 * f + g;
                int col = n0 + wn * 64 + 8 * j + 2 * cq;
                uint32_t h0, l0, h1, l1;
                split2pack(acc[f][j][0], acc[f][j][1], h0, l0);
                split2pack(acc[f][j][2], acc[f][j][3], h1, l1);
                *reinterpret_cast<uint32_t*>(&C2h[(size_t)row * N + col]) = h0;
                *reinterpret_cast<uint32_t*>(&C2l[(size_t)row * N + col]) = l0;
                *reinterpret_cast<uint32_t*>(&C2h[(size_t)(row + 8) * N + col]) = h1;
                *reinterpret_cast<uint32_t*>(&C2l[(size_t)(row + 8) * N + col]) = l1;
            }
    } else {
        float* C = z ? C1 : C0;
#pragma unroll
        for (int f = 0; f < 4; f++)
#pragma unroll
            for (int j = 0; j < 8; j++) {
                int row = m0 + wm * 64 + 16 * f + g;
                int col = n0 + wn * 64 + 8 * j + 2 * cq;
                *reinterpret_cast<float2*>(&C[(size_t)row * N + col]) =
                    make_float2(acc[f][j][0], acc[f][j][1]);
                *reinterpret_cast<float2*>(&C[(size_t)(row + 8) * N + col]) =
                    make_float2(acc[f][j][2], acc[f][j][3]);
            }
    }
}

// ============================================================================
// fp32 -> bf16 hi/lo split (single tensor)
// ============================================================================
__global__ __launch_bounds__(256)
void split_bf16(const float* __restrict__ in, __nv_bfloat16* __restrict__ hi,
                __nv_bfloat16* __restrict__ lo, int n4)
{
    int i = blockIdx.x * blockDim.x + threadIdx.x;
    if (i >= n4) return;
    float4 v = *reinterpret_cast<const float4*>(in + (size_t)i * 4);
    uint32_t h0, l0, h1, l1;
    split2pack(v.x, v.y, h0, l0);
    split2pack(v.z, v.w, h1, l1);
    uint32_t* H = reinterpret_cast<uint32_t*>(hi) + (size_t)i * 2;
    uint32_t* L = reinterpret_cast<uint32_t*>(lo) + (size_t)i * 2;
    H[0] = h0; H[1] = h1; L[0] = l0; L[1] = l1;
}

// ============================================================================
// All-4-weights bf16 hi/lo split in one launch (blockIdx.y = weight index)
// ============================================================================
__global__ __launch_bounds__(256)
void split_w4(const float* __restrict__ W0, const float* __restrict__ W1,
              const float* __restrict__ W2, const float* __restrict__ W3,
              __nv_bfloat16* __restrict__ hiB, __nv_bfloat16* __restrict__ loB)
{
    const int w = blockIdx.y;
    const float* in = (w == 0) ? W0 : (w == 1) ? W1 : (w == 2) ? W2 : W3;
    __nv_bfloat16* hi = hiB + (size_t)w * WSZ;
    __nv_bfloat16* lo = loB + (size_t)w * WSZ;

    int i = blockIdx.x * blockDim.x + threadIdx.x;   // < WSZ/4
    float4 v = *reinterpret_cast<const float4*>(in + (size_t)i * 4);
    uint32_t h0, l0, h1, l1;
    split2pack(v.x, v.y, h0, l0);
    split2pack(v.z, v.w, h1, l1);
    uint32_t* H = reinterpret_cast<uint32_t*>(hi) + (size_t)i * 2;
    uint32_t* L = reinterpret_cast<uint32_t*>(lo) + (size_t)i * 2;
    H[0] = h0; H[1] = h1; L[0] = l0; L[1] = l1;
}

// ============================================================================
// RoPE fused with bf16 hi/lo split; handles Q (y=0) and K (y=1) in one launch.
// ============================================================================
__global__ void init_invfreq()
{
    int i = threadIdx.x;
    g_invfreq[i] = exp(-(double)i * (9.210340371976184 / 64.0));
}

__global__ __launch_bounds__(256)
void rope_split(const float* __restrict__ Qf, const float* __restrict__ Kf,
                __nv_bfloat16* __restrict__ Qhi, __nv_bfloat16* __restrict__ Qlo,
                __nv_bfloat16* __restrict__ Khi, __nv_bfloat16* __restrict__ Klo)
{
    const float* in = blockIdx.y ? Kf : Qf;
    __nv_bfloat16* hi = blockIdx.y ? Khi : Qhi;
    __nv_bfloat16* lo = blockIdx.y ? Klo : Qlo;

    int idx = blockIdx.x * blockDim.x + threadIdx.x;  // [0, B*S*H*64)
    int i = idx & 63;
    int h = (idx >> 6) & (NHEAD - 1);
    int s = (idx >> 10) & (SEQ - 1);
    int b = idx >> 21;

    double inv = g_invfreq[i];
    float ang = (float)((double)s * inv);
    float c, sn;
    sincosf(ang, &sn, &c);

    size_t base = ((size_t)b * SEQ + s) * DIM + (size_t)h * HDIM;
    float x1 = in[base + i];
    float x2 = in[base + 64 + i];
    float y1 = x1 * c - x2 * sn;
    float y2 = x1 * sn + x2 * c;

    __nv_bfloat16 h1 = __float2bfloat16(y1);
    __nv_bfloat16 h2 = __float2bfloat16(y2);
    hi[base + i]      = h1;
    hi[base + 64 + i] = h2;
    lo[base + i]      = __float2bfloat16(y1 - __bfloat162float(h1));
    lo[base + 64 + i] = __float2bfloat16(y2 - __bfloat162float(h2));
}

// ============================================================================
// Tensor-core causal flash attention, bf16x3, fp32 softmax, register P,
// cp.async pipelined K/V. CTA: 128 q-rows; 256 threads = 8 warps x 16 rows.
// Output written directly as bf16 hi/lo (feeds the Wo GEMM).
// ============================================================================
#define FQ_STR 272
#define FQ_H 0
#define FQ_L (FQ_H + 128 * FQ_STR)     // 34816
#define FK_H (FQ_L + 128 * FQ_STR)     // 69632
#define FK_L (FK_H + 64 * FQ_STR)      // 87040
#define FV_H (FK_L + 64 * FQ_STR)      // 104448
#define FV_L (FV_H + 64 * FQ_STR)      // 121856
#define F_SMEM (FV_L + 64 * FQ_STR)    // 139264

__global__ __launch_bounds__(256, 1)
void flash_mma(const __nv_bfloat16* __restrict__ Qh, const __nv_bfloat16* __restrict__ Ql,
               const __nv_bfloat16* __restrict__ Kh, const __nv_bfloat16* __restrict__ Kl,
               const __nv_bfloat16* __restrict__ Vh, const __nv_bfloat16* __restrict__ Vl,
               __nv_bfloat16* __restrict__ Ohi, __nv_bfloat16* __restrict__ Olo)
{
    extern __shared__ __align__(16) char sm[];
    const uint32_t smb = smem_u32(sm);
    const int qt = (int)gridDim.x - 1 - (int)blockIdx.x;  // big tiles first
    const int h  = blockIdx.y;
    const int b  = blockIdx.z;
    const int tid = threadIdx.x;
    const int wid = tid >> 5, lane = tid & 31;
    const int g = lane >> 2, cq = lane & 3;
    const float scale = 0.08838834764831845f;   // 1/sqrt(128)

    const uint32_t aoffQ = (uint32_t)(((lane & 7) + 8 * ((lane >> 3) & 1)) * FQ_STR
                                      + 16 * (lane >> 4));
    const uint32_t boffK = (uint32_t)(((lane & 7) + 8 * (lane >> 4)) * FQ_STR
                                      + 16 * ((lane >> 3) & 1));
    const uint32_t toffV = (uint32_t)(((lane & 7) + 8 * ((lane >> 3) & 1)) * FQ_STR
                                      + 16 * (lane >> 4));

    const size_t rowbase = (size_t)b * SEQ;
    const size_t coloff = (size_t)h * HDIM;
    const int KT = 2 * qt + 2;

    auto load_kv = [&](int kt, bool isK) {
#pragma unroll
        for (int i = 0; i < 4; i++) {
            int s = tid + i * 256;              // 0..1023
            int r = s >> 4, c = s & 15;
            uint32_t so = (uint32_t)(r * FQ_STR + c * 16);
            size_t ga = (rowbase + kt * 64 + r) * DIM + coloff + c * 8;
            if (isK) {
                CP_ASYNC16(smb + FK_H + so, Kh + ga);
                CP_ASYNC16(smb + FK_L + so, Kl + ga);
            } else {
                CP_ASYNC16(smb + FV_H + so, Vh + ga);
                CP_ASYNC16(smb + FV_L + so, Vl + ga);
            }
        }
    };

    // Prologue: group A = Q + K(0); group B = V(0)
#pragma unroll
    for (int i = 0; i < 8; i++) {
        int s = tid + i * 256;                  // 0..2047
        int r = s >> 4, c = s & 15;
        uint32_t so = (uint32_t)(r * FQ_STR + c * 16);
        size_t ga = (rowbase + qt * 128 + r) * DIM + coloff + c * 8;
        CP_ASYNC16(smb + FQ_H + so, Qh + ga);
        CP_ASYNC16(smb + FQ_L + so, Ql + ga);
    }
    load_kv(0, true);
    CP_COMMIT();
    load_kv(0, false);
    CP_COMMIT();

    float oacc[16][4];
#pragma unroll
    for (int f = 0; f < 16; f++)
#pragma unroll
        for (int v = 0; v < 4; v++) oacc[f][v] = 0.f;
    float m0 = -1e30f, m1 = -1e30f, l0 = 0.f, l1 = 0.f;

    for (int kt = 0; kt < KT; kt++) {
        const int ktn = (kt + 1 < KT) ? kt + 1 : kt;

        CP_WAIT1();            // K(kt) (and Q at kt=0) landed
        __syncthreads();

        // ---- S = Q K^T (bf16x3) ----
        float sacc[8][4];
#pragma unroll
        for (int j = 0; j < 8; j++)
#pragma unroll
            for (int v = 0; v < 4; v++) sacc[j][v] = 0.f;

        const uint32_t qrow = (uint32_t)(wid * 16 * FQ_STR);
#pragma unroll
        for (int ks = 0; ks < 8; ks++) {
            const uint32_t kso = (uint32_t)(32 * ks);
            uint32_t ah_[4], al_[4], bh_[4][4];
            ldsm_x4(ah_, smb + FQ_H + qrow + aoffQ + kso);
            ldsm_x4(al_, smb + FQ_L + qrow + aoffQ + kso);
#pragma unroll
            for (int J = 0; J < 4; J++)
                ldsm_x4(bh_[J], smb + FK_H + (uint32_t)(J * 16 * FQ_STR) + boffK + kso);
#pragma unroll
            for (int J = 0; J < 4; J++) {
                mma_bf16(sacc[2 * J + 0], ah_, bh_[J][0], bh_[J][1]);
                mma_bf16(sacc[2 * J + 1], ah_, bh_[J][2], bh_[J][3]);
            }
#pragma unroll
            for (int J = 0; J < 4; J++) {
                mma_bf16(sacc[2 * J + 0], al_, bh_[J][0], bh_[J][1]);
                mma_bf16(sacc[2 * J + 1], al_, bh_[J][2], bh_[J][3]);
            }
#pragma unroll
            for (int J = 0; J < 4; J++) {
                uint32_t bl_[4];
                ldsm_x4(bl_, smb + FK_L + (uint32_t)(J * 16 * FQ_STR) + boffK + kso);
                mma_bf16(sacc[2 * J + 0], ah_, bl_[0], bl_[1]);
                mma_bf16(sacc[2 * J + 1], ah_, bl_[2], bl_[3]);
            }
        }
        __syncthreads();       // all warps done with K smem
        load_kv(ktn, true);    // prefetch K(kt+1) during softmax+PV
        CP_COMMIT();

        // ---- scale + causal mask ----
        const int row0 = qt * 128 + wid * 16 + g;
        const int row1 = row0 + 8;
        const bool diag = (kt >= 2 * qt);
#pragma unroll
        for (int j = 0; j < 8; j++) {
            int colb = kt * 64 + 8 * j + 2 * cq;
#pragma unroll
            for (int v = 0; v < 4; v++) sacc[j][v] *= scale;
            if (diag) {
                if (colb     > row0) sacc[j][0] = -1e30f;
                if (colb + 1 > row0) sacc[j][1] = -1e30f;
                if (colb     > row1) sacc[j][2] = -1e30f;
                if (colb + 1 > row1) sacc[j][3] = -1e30f;
            }
        }

        // ---- online softmax + register-resident P fragments ----
        float mt0 = -1e30f, mt1 = -1e30f;
#pragma unroll
        for (int j = 0; j < 8; j++) {
            mt0 = fmaxf(mt0, fmaxf(sacc[j][0], sacc[j][1]));
            mt1 = fmaxf(mt1, fmaxf(sacc[j][2], sacc[j][3]));
        }
        mt0 = fmaxf(mt0, __shfl_xor_sync(0xffffffffu, mt0, 1));
        mt0 = fmaxf(mt0, __shfl_xor_sync(0xffffffffu, mt0, 2));
        mt1 = fmaxf(mt1, __shfl_xor_sync(0xffffffffu, mt1, 1));
        mt1 = fmaxf(mt1, __shfl_xor_sync(0xffffffffu, mt1, 2));

        float mn0 = fmaxf(m0, mt0), mn1 = fmaxf(m1, mt1);
        float a0 = __expf(m0 - mn0), a1 = __expf(m1 - mn1);
        m0 = mn0; m1 = mn1;

        uint32_t ph0[8], ph1[8], pl0[8], pl1[8];
        float ls0 = 0.f, ls1 = 0.f;
#pragma unroll
        for (int j = 0; j < 8; j++) {
            float p0 = __expf(sacc[j][0] - mn0);
            float p1 = __expf(sacc[j][1] - mn0);
            float p2 = __expf(sacc[j][2] - mn1);
            float p3 = __expf(sacc[j][3] - mn1);
            ls0 += p0 + p1; ls1 += p2 + p3;
            split2pack(p0, p1, ph0[j], pl0[j]);
            split2pack(p2, p3, ph1[j], pl1[j]);
        }
        ls0 += __shfl_xor_sync(0xffffffffu, ls0, 1);
        ls0 += __shfl_xor_sync(0xffffffffu, ls0, 2);
        ls1 += __shfl_xor_sync(0xffffffffu, ls1, 1);
        ls1 += __shfl_xor_sync(0xffffffffu, ls1, 2);
        l0 = l0 * a0 + ls0;
        l1 = l1 * a1 + ls1;
#pragma unroll
        for (int f = 0; f < 16; f++) {
            oacc[f][0] *= a0; oacc[f][1] *= a0;
            oacc[f][2] *= a1; oacc[f][3] *= a1;
        }

        CP_WAIT1();            // V(kt) landed
        __syncthreads();

        // ---- O += P V (bf16x3, register P) ----
#pragma unroll
        for (int ks = 0; ks < 4; ks++) {
            uint32_t a_h[4] = {ph0[2 * ks], ph1[2 * ks], ph0[2 * ks + 1], ph1[2 * ks + 1]};
            uint32_t a_l[4] = {pl0[2 * ks], pl1[2 * ks], pl0[2 * ks + 1], pl1[2 * ks + 1]};
            const uint32_t vrow = (uint32_t)(ks * 16 * FQ_STR);
            uint32_t vv[8][4];
#pragma unroll
            for (int J = 0; J < 8; J++)
                ldsm_x4_t(vv[J], smb + FV_H + vrow + (uint32_t)(J * 32) + toffV);
#pragma unroll
            for (int J = 0; J < 8; J++) {
                mma_bf16(oacc[2 * J + 0], a_h, vv[J][0], vv[J][1]);
                mma_bf16(oacc[2 * J + 1], a_h, vv[J][2], vv[J][3]);
            }
#pragma unroll
            for (int J = 0; J < 8; J++) {
                mma_bf16(oacc[2 * J + 0], a_l, vv[J][0], vv[J][1]);
                mma_bf16(oacc[2 * J + 1], a_l, vv[J][2], vv[J][3]);
            }
#pragma unroll
            for (int J = 0; J < 8; J++)
                ldsm_x4_t(vv[J], smb + FV_L + vrow + (uint32_t)(J * 32) + toffV);
#pragma unroll
            for (int J = 0; J < 8; J++) {
                mma_bf16(oacc[2 * J + 0], a_h, vv[J][0], vv[J][1]);
                mma_bf16(oacc[2 * J + 1], a_h, vv[J][2], vv[J][3]);
            }
        }
        __syncthreads();       // all warps done with V smem
        load_kv(ktn, false);   // prefetch V(kt+1) during next QK
        CP_COMMIT();
    }
    CP_WAIT0();

    // ---- normalize + write O as bf16 hi/lo ----
    const float inv0 = 1.f / l0, inv1 = 1.f / l1;
    const int r0g = qt * 128 + wid * 16 + g;
#pragma unroll
    for (int f = 0; f < 16; f++) {
        int col = 8 * f + 2 * cq;
        size_t b0a = (rowbase + r0g) * DIM + coloff + col;
        size_t b1a = (rowbase + r0g + 8) * DIM + coloff + col;
        uint32_t h0, lo0, h1, lo1;
        split2pack(oacc[f][0] * inv0, oacc[f][1] * inv0, h0, lo0);
        split2pack(oacc[f][2] * inv1, oacc[f][3] * inv1, h1, lo1);
        *reinterpret_cast<uint32_t*>(&Ohi[b0a]) = h0;
        *reinterpret_cast<uint32_t*>(&Olo[b0a]) = lo0;
        *reinterpret_cast<uint32_t*>(&Ohi[b1a]) = h1;
        *reinterpret_cast<uint32_t*>(&Olo[b1a]) = lo1;
    }
}

// ============================================================================
// Launch
// ============================================================================
extern "C" void kernel_launch(void* const* d_in, const int* in_sizes, int n_in,
                              void* d_out, int out_size)
{
    (void)in_sizes; (void)n_in; (void)out_size;
    const float* x  = (const float*)d_in[0];
    const float* Wq = (const float*)d_in[1];
    const float* Wk = (const float*)d_in[2];
    const float* Wv = (const float*)d_in[3];
    const float* Wo = (const float*)d_in[4];
    float* out = (float*)d_out;

    float *Qp, *Kp;
    __nv_bfloat16 *ah, *al, *bh, *bl, *qh, *ql, *kh, *kl, *vh, *vl;
    cudaGetSymbolAddress((void**)&Qp, g_Q);
    cudaGetSymbolAddress((void**)&Kp, g_K);
    cudaGetSymbolAddress((void**)&ah, g_ah);
    cudaGetSymbolAddress((void**)&al, g_al);
    cudaGetSymbolAddress((void**)&bh, g_bh);
    cudaGetSymbolAddress((void**)&bl, g_bl);
    cudaGetSymbolAddress((void**)&qh, g_qh);
    cudaGetSymbolAddress((void**)&ql, g_ql);
    cudaGetSymbolAddress((void**)&kh, g_kh);
    cudaGetSymbolAddress((void**)&kl, g_kl);
    cudaGetSymbolAddress((void**)&vh, g_vh);
    cudaGetSymbolAddress((void**)&vl, g_vl);

    cudaFuncSetAttribute(gemm_mma, cudaFuncAttributeMaxDynamicSharedMemorySize,
                         G_SMEM);
    cudaFuncSetAttribute(flash_mma, cudaFuncAttributeMaxDynamicSharedMemorySize,
                         F_SMEM);

    const int nx4 = (int)(ELEMS / 4);
    const int nw4 = (int)(WSZ / 4);

    init_invfreq<<<1, 64>>>();

    // All weight splits in one launch; x split
    split_w4<<<dim3(nw4 / 256, 4), 256>>>(Wq, Wk, Wv, Wo, bh, bl);
    split_bf16<<<(nx4 + 255) / 256, 256>>>(x, ah, al, nx4);

    // Fused QKV projection: z=0 -> Q (fp32), z=1 -> K (fp32), z=2 -> V (bf16)
    gemm_mma<<<dim3(DIM / 128, MTOT / 128, 3), 128, G_SMEM>>>(
        ah, al, bh, bl, Qp, Kp, vh, vl, MTOT, DIM, DIM);

    // RoPE + split for Q and K in one launch
    int rope_blocks = (BATCH * SEQ * NHEAD * 64) / 256;   // 16384
    rope_split<<<dim3(rope_blocks, 2), 256>>>(Qp, Kp, qh, ql, kh, kl);

    // Tensor-core causal flash attention -> writes ah/al (bf16 hi/lo)
    flash_mma<<<dim3(SEQ / 128, NHEAD, BATCH), 256, F_SMEM>>>(qh, ql, kh, kl,
                                                              vh, vl, ah, al);

    // Output projection (weight slice 3); z=0 path writes fp32 to out
    gemm_mma<<<dim3(DIM / 128, MTOT / 128, 1), 128, G_SMEM>>>(
        ah, al, bh + 3 * WSZ, bl + 3 * WSZ, out, nullptr, nullptr, nullptr,
        MTOT, DIM, DIM);
}

// round 17
// speedup vs baseline: 1.6207x; 1.6207x over previous
#include <cuda_runtime.h>
#include <cuda_bf16.h>
#include <math.h>
#include <stdint.h>

// Problem constants
#define BATCH 2
#define SEQ   2048
#define DIM   2048
#define NHEAD 16
#define HDIM  128
#define MTOT  (BATCH * SEQ)      // 4096 rows
#define ELEMS ((size_t)BATCH * SEQ * DIM)   // 8388608
#define WSZ   ((size_t)DIM * DIM)           // 4194304

// ---------------- scratch (no allocations allowed) ----------------
__device__ float g_Q[ELEMS];
__device__ float g_K[ELEMS];
__device__ __align__(16) __nv_bfloat16 g_ah[ELEMS];          // A hi (x, then attn-out)
__device__ __align__(16) __nv_bfloat16 g_al[ELEMS];          // A lo
__device__ __align__(16) __nv_bfloat16 g_bh[4 * WSZ];        // Wq,Wk,Wv,Wo hi
__device__ __align__(16) __nv_bfloat16 g_bl[4 * WSZ];        // Wq,Wk,Wv,Wo lo
__device__ __align__(16) __nv_bfloat16 g_qh[ELEMS];
__device__ __align__(16) __nv_bfloat16 g_ql[ELEMS];
__device__ __align__(16) __nv_bfloat16 g_kh[ELEMS];
__device__ __align__(16) __nv_bfloat16 g_kl[ELEMS];
__device__ __align__(16) __nv_bfloat16 g_vh[ELEMS];
__device__ __align__(16) __nv_bfloat16 g_vl[ELEMS];
__device__ double g_invfreq[64];

// ============================================================================
// mma.sync / ldmatrix / cp.async helpers (all legal at compute_103)
// ============================================================================
__device__ __forceinline__ uint32_t smem_u32(const void* p) {
    uint32_t a;
    asm("{ .reg .u64 t; cvta.to.shared.u64 t, %1; cvt.u32.u64 %0, t; }"
        : "=r"(a) : "l"(p));
    return a;
}

__device__ __forceinline__ void ldsm_x4(uint32_t (&r)[4], uint32_t addr) {
    asm volatile("ldmatrix.sync.aligned.m8n8.x4.shared.b16 {%0,%1,%2,%3}, [%4];"
                 : "=r"(r[0]), "=r"(r[1]), "=r"(r[2]), "=r"(r[3]) : "r"(addr));
}

__device__ __forceinline__ void ldsm_x4_t(uint32_t (&r)[4], uint32_t addr) {
    asm volatile("ldmatrix.sync.aligned.m8n8.x4.trans.shared.b16 {%0,%1,%2,%3}, [%4];"
                 : "=r"(r[0]), "=r"(r[1]), "=r"(r[2]), "=r"(r[3]) : "r"(addr));
}

__device__ __forceinline__ void mma_bf16(float (&c)[4], const uint32_t (&a)[4],
                                         uint32_t b0, uint32_t b1) {
    asm volatile(
        "mma.sync.aligned.m16n8k16.row.col.f32.bf16.bf16.f32 "
        "{%0,%1,%2,%3}, {%4,%5,%6,%7}, {%8,%9}, {%0,%1,%2,%3};"
        : "+f"(c[0]), "+f"(c[1]), "+f"(c[2]), "+f"(c[3])
        : "r"(a[0]), "r"(a[1]), "r"(a[2]), "r"(a[3]), "r"(b0), "r"(b1));
}

#define CP_ASYNC16(dst, src) \
    asm volatile("cp.async.ca.shared.global [%0], [%1], 16;" \
                 :: "r"(dst), "l"(src) : "memory")
#define CP_COMMIT() asm volatile("cp.async.commit_group;" ::: "memory")
#define CP_WAIT0()  asm volatile("cp.async.wait_group 0;" ::: "memory")
#define CP_WAIT1()  asm volatile("cp.async.wait_group 1;" ::: "memory")

// hi/lo bf16 pair packing
__device__ __forceinline__ void split2pack(float a, float b, uint32_t& h, uint32_t& l) {
    __nv_bfloat16 ha = __float2bfloat16(a), hb = __float2bfloat16(b);
    __nv_bfloat162 th(ha, hb);
    h = *reinterpret_cast<uint32_t*>(&th);
    __nv_bfloat162 tl(__float2bfloat16(a - __bfloat162float(ha)),
                      __float2bfloat16(b - __bfloat162float(hb)));
    l = *reinterpret_cast<uint32_t*>(&tl);
}

// ============================================================================
// bf16x3 tensor-core GEMM (NT): C[m,n] = sum_k A[m,k]*B[n,k]
// CTA tile 128x128, BK=32, 128 threads = 4 warps (2m x 2n), warp tile 64x64.
// blockIdx.z selects weight slice z and output destination:
//   z=0 -> fp32 C0, z=1 -> fp32 C1, z=2 -> bf16 hi/lo C2h/C2l.
// Inner loop: ALL 16 fragment ldsm hoisted before an uninterrupted 48-mma
// burst per k16-step. 2 CTAs/SM. Double-buffered cp.async.  (R14 proven)
// ============================================================================
#define G_TILE_B (128 * 80)               // 10240 B per tile
#define TA_H 0
#define TA_L (G_TILE_B)
#define TB_H (2 * G_TILE_B)
#define TB_L (3 * G_TILE_B)
#define G_STAGE (4 * G_TILE_B)            // 40960 per stage
#define G_SMEM (2 * G_STAGE)              // 81920

__global__ __launch_bounds__(128, 2)
void gemm_mma(const __nv_bfloat16* __restrict__ Ah, const __nv_bfloat16* __restrict__ Al,
              const __nv_bfloat16* __restrict__ BhBase,
              const __nv_bfloat16* __restrict__ BlBase,
              float* __restrict__ C0, float* __restrict__ C1,
              __nv_bfloat16* __restrict__ C2h, __nv_bfloat16* __restrict__ C2l,
              int M, int N, int K)
{
    extern __shared__ __align__(16) char sm[];
    const uint32_t smb = smem_u32(sm);
    const int tid = threadIdx.x;
    const int wid = tid >> 5, lane = tid & 31;
    const int wm = wid & 1, wn = wid >> 1;            // 2 x 2 warp grid
    const int m0 = blockIdx.y * 128, n0 = blockIdx.x * 128;
    const int z = blockIdx.z;
    const __nv_bfloat16* Bh = BhBase + (size_t)z * WSZ;
    const __nv_bfloat16* Bl = BlBase + (size_t)z * WSZ;

    const uint32_t aoff = (uint32_t)(((lane & 7) + 8 * ((lane >> 3) & 1)) * 80
                                     + 16 * (lane >> 4));
    const uint32_t boff = (uint32_t)(((lane & 7) + 8 * (lane >> 4)) * 80
                                     + 16 * ((lane >> 3) & 1));

    const int lr = tid >> 2, lc = tid & 3;

    auto load_tiles = [&](int kb, int st) {
        uint32_t base = smb + (uint32_t)(st * G_STAGE);
#pragma unroll
        for (int i = 0; i < 4; i++) {
            int r = lr + 32 * i;
            uint32_t so = (uint32_t)(r * 80 + lc * 16);
            size_t ga = (size_t)(m0 + r) * K + (size_t)kb * 32 + lc * 8;
            size_t gb = (size_t)(n0 + r) * K + (size_t)kb * 32 + lc * 8;
            CP_ASYNC16(base + TA_H + so, Ah + ga);
            CP_ASYNC16(base + TA_L + so, Al + ga);
            CP_ASYNC16(base + TB_H + so, Bh + gb);
            CP_ASYNC16(base + TB_L + so, Bl + gb);
        }
        CP_COMMIT();
    };

    float acc[4][8][4];
#pragma unroll
    for (int i = 0; i < 4; i++)
#pragma unroll
        for (int j = 0; j < 8; j++)
#pragma unroll
            for (int v = 0; v < 4; v++) acc[i][j][v] = 0.f;

    const int KB = K >> 5;
    load_tiles(0, 0);
    int st = 0;
    for (int kb = 0; kb < KB; kb++) {
        CP_WAIT0();
        __syncthreads();
        if (kb + 1 < KB) load_tiles(kb + 1, st ^ 1);

        const uint32_t sb = smb + (uint32_t)(st * G_STAGE);
#pragma unroll
        for (int ks = 0; ks < 2; ks++) {
            const uint32_t kso = (uint32_t)(32 * ks);
            uint32_t ah_[4][4], al_[4][4], bhf[4][4], blf[4][4];
            // hoist ALL fragment loads (16 ldsm) ...
#pragma unroll
            for (int f = 0; f < 4; f++) {
                uint32_t ro = (uint32_t)((wm * 64 + 16 * f) * 80);
                ldsm_x4(ah_[f], sb + TA_H + ro + aoff + kso);
                ldsm_x4(al_[f], sb + TA_L + ro + aoff + kso);
            }
#pragma unroll
            for (int j = 0; j < 4; j++) {
                uint32_t ro = (uint32_t)((wn * 64 + 16 * j) * 80);
                ldsm_x4(bhf[j], sb + TB_H + ro + boff + kso);
                ldsm_x4(blf[j], sb + TB_L + ro + boff + kso);
            }
            // ... then one uninterrupted 48-mma burst (32 indep accumulators)
#pragma unroll
            for (int f = 0; f < 4; f++)
#pragma unroll
                for (int j = 0; j < 4; j++) {
                    mma_bf16(acc[f][2 * j + 0], ah_[f], bhf[j][0], bhf[j][1]);
                    mma_bf16(acc[f][2 * j + 1], ah_[f], bhf[j][2], bhf[j][3]);
                }
#pragma unroll
            for (int f = 0; f < 4; f++)
#pragma unroll
                for (int j = 0; j < 4; j++) {
                    mma_bf16(acc[f][2 * j + 0], al_[f], bhf[j][0], bhf[j][1]);
                    mma_bf16(acc[f][2 * j + 1], al_[f], bhf[j][2], bhf[j][3]);
                }
#pragma unroll
            for (int f = 0; f < 4; f++)
#pragma unroll
                for (int j = 0; j < 4; j++) {
                    mma_bf16(acc[f][2 * j + 0], ah_[f], blf[j][0], blf[j][1]);
                    mma_bf16(acc[f][2 * j + 1], ah_[f], blf[j][2], blf[j][3]);
                }
        }
        st ^= 1;
    }

    const int g = lane >> 2, cq = lane & 3;
    if (z == 2) {
#pragma unroll
        for (int f = 0; f < 4; f++)
#pragma unroll
            for (int j = 0; j < 8; j++) {
                int row = m0 + wm * 64 + 16 * f + g;
                int col = n0 + wn * 64 + 8 * j + 2 * cq;
                uint32_t h0, l0, h1, l1;
                split2pack(acc[f][j][0], acc[f][j][1], h0, l0);
                split2pack(acc[f][j][2], acc[f][j][3], h1, l1);
                *reinterpret_cast<uint32_t*>(&C2h[(size_t)row * N + col]) = h0;
                *reinterpret_cast<uint32_t*>(&C2l[(size_t)row * N + col]) = l0;
                *reinterpret_cast<uint32_t*>(&C2h[(size_t)(row + 8) * N + col]) = h1;
                *reinterpret_cast<uint32_t*>(&C2l[(size_t)(row + 8) * N + col]) = l1;
            }
    } else {
        float* C = z ? C1 : C0;
#pragma unroll
        for (int f = 0; f < 4; f++)
#pragma unroll
            for (int j = 0; j < 8; j++) {
                int row = m0 + wm * 64 + 16 * f + g;
                int col = n0 + wn * 64 + 8 * j + 2 * cq;
                *reinterpret_cast<float2*>(&C[(size_t)row * N + col]) =
                    make_float2(acc[f][j][0], acc[f][j][1]);
                *reinterpret_cast<float2*>(&C[(size_t)(row + 8) * N + col]) =
                    make_float2(acc[f][j][2], acc[f][j][3]);
            }
    }
}

// ============================================================================
// fp32 -> bf16 hi/lo split (single tensor)
// ============================================================================
__global__ __launch_bounds__(256)
void split_bf16(const float* __restrict__ in, __nv_bfloat16* __restrict__ hi,
                __nv_bfloat16* __restrict__ lo, int n4)
{
    int i = blockIdx.x * blockDim.x + threadIdx.x;
    if (i >= n4) return;
    float4 v = *reinterpret_cast<const float4*>(in + (size_t)i * 4);
    uint32_t h0, l0, h1, l1;
    split2pack(v.x, v.y, h0, l0);
    split2pack(v.z, v.w, h1, l1);
    uint32_t* H = reinterpret_cast<uint32_t*>(hi) + (size_t)i * 2;
    uint32_t* L = reinterpret_cast<uint32_t*>(lo) + (size_t)i * 2;
    H[0] = h0; H[1] = h1; L[0] = l0; L[1] = l1;
}

// ============================================================================
// All-4-weights bf16 hi/lo split in one launch (blockIdx.y = weight index)
// ============================================================================
__global__ __launch_bounds__(256)
void split_w4(const float* __restrict__ W0, const float* __restrict__ W1,
              const float* __restrict__ W2, const float* __restrict__ W3,
              __nv_bfloat16* __restrict__ hiB, __nv_bfloat16* __restrict__ loB)
{
    const int w = blockIdx.y;
    const float* in = (w == 0) ? W0 : (w == 1) ? W1 : (w == 2) ? W2 : W3;
    __nv_bfloat16* hi = hiB + (size_t)w * WSZ;
    __nv_bfloat16* lo = loB + (size_t)w * WSZ;

    int i = blockIdx.x * blockDim.x + threadIdx.x;   // < WSZ/4
    float4 v = *reinterpret_cast<const float4*>(in + (size_t)i * 4);
    uint32_t h0, l0, h1, l1;
    split2pack(v.x, v.y, h0, l0);
    split2pack(v.z, v.w, h1, l1);
    uint32_t* H = reinterpret_cast<uint32_t*>(hi) + (size_t)i * 2;
    uint32_t* L = reinterpret_cast<uint32_t*>(lo) + (size_t)i * 2;
    H[0] = h0; H[1] = h1; L[0] = l0; L[1] = l1;
}

// ============================================================================
// RoPE fused with bf16 hi/lo split; handles Q (y=0) and K (y=1) in one launch.
// ============================================================================
__global__ void init_invfreq()
{
    int i = threadIdx.x;
    g_invfreq[i] = exp(-(double)i * (9.210340371976184 / 64.0));
}

__global__ __launch_bounds__(256)
void rope_split(const float* __restrict__ Qf, const float* __restrict__ Kf,
                __nv_bfloat16* __restrict__ Qhi, __nv_bfloat16* __restrict__ Qlo,
                __nv_bfloat16* __restrict__ Khi, __nv_bfloat16* __restrict__ Klo)
{
    const float* in = blockIdx.y ? Kf : Qf;
    __nv_bfloat16* hi = blockIdx.y ? Khi : Qhi;
    __nv_bfloat16* lo = blockIdx.y ? Klo : Qlo;

    int idx = blockIdx.x * blockDim.x + threadIdx.x;  // [0, B*S*H*64)
    int i = idx & 63;
    int h = (idx >> 6) & (NHEAD - 1);
    int s = (idx >> 10) & (SEQ - 1);
    int b = idx >> 21;

    double inv = g_invfreq[i];
    float ang = (float)((double)s * inv);
    float c, sn;
    sincosf(ang, &sn, &c);

    size_t base = ((size_t)b * SEQ + s) * DIM + (size_t)h * HDIM;
    float x1 = in[base + i];
    float x2 = in[base + 64 + i];
    float y1 = x1 * c - x2 * sn;
    float y2 = x1 * sn + x2 * c;

    __nv_bfloat16 h1 = __float2bfloat16(y1);
    __nv_bfloat16 h2 = __float2bfloat16(y2);
    hi[base + i]      = h1;
    hi[base + 64 + i] = h2;
    lo[base + i]      = __float2bfloat16(y1 - __bfloat162float(h1));
    lo[base + 64 + i] = __float2bfloat16(y2 - __bfloat162float(h2));
}

// ============================================================================
// Tensor-core causal flash attention, bf16x3, fp32 softmax, register P,
// cp.async pipelined K/V. CTA: 64 q-rows; 128 threads = 4 warps x 16 rows.
// 2 CTAs/SM (smem 104448 x2 = 208896 <= 227KB). K-tiles of 64 (KT = qt+1).
// Per-warp code identical to the 1447us version; only the CTA shape changed.
// Output written directly as bf16 hi/lo (feeds the Wo GEMM).
// ============================================================================
#define FQ_STR 272
#define FQ_H 0
#define FQ_L (FQ_H + 64 * FQ_STR)      // 17408
#define FK_H (FQ_L + 64 * FQ_STR)      // 34816
#define FK_L (FK_H + 64 * FQ_STR)      // 52224
#define FV_H (FK_L + 64 * FQ_STR)      // 69632
#define FV_L (FV_H + 64 * FQ_STR)      // 87040
#define F_SMEM (FV_L + 64 * FQ_STR)    // 104448

__global__ __launch_bounds__(128, 2)
void flash_mma(const __nv_bfloat16* __restrict__ Qh, const __nv_bfloat16* __restrict__ Ql,
               const __nv_bfloat16* __restrict__ Kh, const __nv_bfloat16* __restrict__ Kl,
               const __nv_bfloat16* __restrict__ Vh, const __nv_bfloat16* __restrict__ Vl,
               __nv_bfloat16* __restrict__ Ohi, __nv_bfloat16* __restrict__ Olo)
{
    extern __shared__ __align__(16) char sm[];
    const uint32_t smb = smem_u32(sm);
    const int qt = (int)gridDim.x - 1 - (int)blockIdx.x;  // big tiles first
    const int h  = blockIdx.y;
    const int b  = blockIdx.z;
    const int tid = threadIdx.x;
    const int wid = tid >> 5, lane = tid & 31;            // wid 0..3
    const int g = lane >> 2, cq = lane & 3;
    const float scale = 0.08838834764831845f;   // 1/sqrt(128)

    const uint32_t aoffQ = (uint32_t)(((lane & 7) + 8 * ((lane >> 3) & 1)) * FQ_STR
                                      + 16 * (lane >> 4));
    const uint32_t boffK = (uint32_t)(((lane & 7) + 8 * (lane >> 4)) * FQ_STR
                                      + 16 * ((lane >> 3) & 1));
    const uint32_t toffV = (uint32_t)(((lane & 7) + 8 * ((lane >> 3) & 1)) * FQ_STR
                                      + 16 * (lane >> 4));

    const size_t rowbase = (size_t)b * SEQ;
    const size_t coloff = (size_t)h * HDIM;
    const int KT = qt + 1;

    auto load_kv = [&](int kt, bool isK) {
#pragma unroll
        for (int i = 0; i < 8; i++) {
            int s = tid + i * 128;              // 0..1023
            int r = s >> 4, c = s & 15;
            uint32_t so = (uint32_t)(r * FQ_STR + c * 16);
            size_t ga = (rowbase + kt * 64 + r) * DIM + coloff + c * 8;
            if (isK) {
                CP_ASYNC16(smb + FK_H + so, Kh + ga);
                CP_ASYNC16(smb + FK_L + so, Kl + ga);
            } else {
                CP_ASYNC16(smb + FV_H + so, Vh + ga);
                CP_ASYNC16(smb + FV_L + so, Vl + ga);
            }
        }
    };

    // Prologue: group A = Q + K(0); group B = V(0)
#pragma unroll
    for (int i = 0; i < 8; i++) {
        int s = tid + i * 128;                  // 0..1023
        int r = s >> 4, c = s & 15;
        uint32_t so = (uint32_t)(r * FQ_STR + c * 16);
        size_t ga = (rowbase + qt * 64 + r) * DIM + coloff + c * 8;
        CP_ASYNC16(smb + FQ_H + so, Qh + ga);
        CP_ASYNC16(smb + FQ_L + so, Ql + ga);
    }
    load_kv(0, true);
    CP_COMMIT();
    load_kv(0, false);
    CP_COMMIT();

    float oacc[16][4];
#pragma unroll
    for (int f = 0; f < 16; f++)
#pragma unroll
        for (int v = 0; v < 4; v++) oacc[f][v] = 0.f;
    float m0 = -1e30f, m1 = -1e30f, l0 = 0.f, l1 = 0.f;

    for (int kt = 0; kt < KT; kt++) {
        const int ktn = (kt + 1 < KT) ? kt + 1 : kt;

        CP_WAIT1();            // K(kt) (and Q at kt=0) landed
        __syncthreads();

        // ---- S = Q K^T (bf16x3) ----
        float sacc[8][4];
#pragma unroll
        for (int j = 0; j < 8; j++)
#pragma unroll
            for (int v = 0; v < 4; v++) sacc[j][v] = 0.f;

        const uint32_t qrow = (uint32_t)(wid * 16 * FQ_STR);
#pragma unroll
        for (int ks = 0; ks < 8; ks++) {
            const uint32_t kso = (uint32_t)(32 * ks);
            uint32_t ah_[4], al_[4], bh_[4][4];
            ldsm_x4(ah_, smb + FQ_H + qrow + aoffQ + kso);
            ldsm_x4(al_, smb + FQ_L + qrow + aoffQ + kso);
#pragma unroll
            for (int J = 0; J < 4; J++)
                ldsm_x4(bh_[J], smb + FK_H + (uint32_t)(J * 16 * FQ_STR) + boffK + kso);
#pragma unroll
            for (int J = 0; J < 4; J++) {
                mma_bf16(sacc[2 * J + 0], ah_, bh_[J][0], bh_[J][1]);
                mma_bf16(sacc[2 * J + 1], ah_, bh_[J][2], bh_[J][3]);
            }
#pragma unroll
            for (int J = 0; J < 4; J++) {
                mma_bf16(sacc[2 * J + 0], al_, bh_[J][0], bh_[J][1]);
                mma_bf16(sacc[2 * J + 1], al_, bh_[J][2], bh_[J][3]);
            }
#pragma unroll
            for (int J = 0; J < 4; J++) {
                uint32_t bl_[4];
                ldsm_x4(bl_, smb + FK_L + (uint32_t)(J * 16 * FQ_STR) + boffK + kso);
                mma_bf16(sacc[2 * J + 0], ah_, bl_[0], bl_[1]);
                mma_bf16(sacc[2 * J + 1], ah_, bl_[2], bl_[3]);
            }
        }
        __syncthreads();       // all warps done with K smem
        load_kv(ktn, true);    // prefetch K(kt+1) during softmax+PV
        CP_COMMIT();

        // ---- scale + causal mask ----
        const int row0 = qt * 64 + wid * 16 + g;
        const int row1 = row0 + 8;
        const bool diag = (kt == qt);
#pragma unroll
        for (int j = 0; j < 8; j++) {
            int colb = kt * 64 + 8 * j + 2 * cq;
#pragma unroll
            for (int v = 0; v < 4; v++) sacc[j][v] *= scale;
            if (diag) {
                if (colb     > row0) sacc[j][0] = -1e30f;
                if (colb + 1 > row0) sacc[j][1] = -1e30f;
                if (colb     > row1) sacc[j][2] = -1e30f;
                if (colb + 1 > row1) sacc[j][3] = -1e30f;
            }
        }

        // ---- online softmax + register-resident P fragments ----
        float mt0 = -1e30f, mt1 = -1e30f;
#pragma unroll
        for (int j = 0; j < 8; j++) {
            mt0 = fmaxf(mt0, fmaxf(sacc[j][0], sacc[j][1]));
            mt1 = fmaxf(mt1, fmaxf(sacc[j][2], sacc[j][3]));
        }
        mt0 = fmaxf(mt0, __shfl_xor_sync(0xffffffffu, mt0, 1));
        mt0 = fmaxf(mt0, __shfl_xor_sync(0xffffffffu, mt0, 2));
        mt1 = fmaxf(mt1, __shfl_xor_sync(0xffffffffu, mt1, 1));
        mt1 = fmaxf(mt1, __shfl_xor_sync(0xffffffffu, mt1, 2));

        float mn0 = fmaxf(m0, mt0), mn1 = fmaxf(m1, mt1);
        float a0 = __expf(m0 - mn0), a1 = __expf(m1 - mn1);
        m0 = mn0; m1 = mn1;

        uint32_t ph0[8], ph1[8], pl0[8], pl1[8];
        float ls0 = 0.f, ls1 = 0.f;
#pragma unroll
        for (int j = 0; j < 8; j++) {
            float p0 = __expf(sacc[j][0] - mn0);
            float p1 = __expf(sacc[j][1] - mn0);
            float p2 = __expf(sacc[j][2] - mn1);
            float p3 = __expf(sacc[j][3] - mn1);
            ls0 += p0 + p1; ls1 += p2 + p3;
            split2pack(p0, p1, ph0[j], pl0[j]);
            split2pack(p2, p3, ph1[j], pl1[j]);
        }
        ls0 += __shfl_xor_sync(0xffffffffu, ls0, 1);
        ls0 += __shfl_xor_sync(0xffffffffu, ls0, 2);
        ls1 += __shfl_xor_sync(0xffffffffu, ls1, 1);
        ls1 += __shfl_xor_sync(0xffffffffu, ls1, 2);
        l0 = l0 * a0 + ls0;
        l1 = l1 * a1 + ls1;
#pragma unroll
        for (int f = 0; f < 16; f++) {
            oacc[f][0] *= a0; oacc[f][1] *= a0;
            oacc[f][2] *= a1; oacc[f][3] *= a1;
        }

        CP_WAIT1();            // V(kt) landed
        __syncthreads();

        // ---- O += P V (bf16x3, register P) ----
#pragma unroll
        for (int ks = 0; ks < 4; ks++) {
            uint32_t a_h[4] = {ph0[2 * ks], ph1[2 * ks], ph0[2 * ks + 1], ph1[2 * ks + 1]};
            uint32_t a_l[4] = {pl0[2 * ks], pl1[2 * ks], pl0[2 * ks + 1], pl1[2 * ks + 1]};
            const uint32_t vrow = (uint32_t)(ks * 16 * FQ_STR);
            uint32_t vv[8][4];
#pragma unroll
            for (int J = 0; J < 8; J++)
                ldsm_x4_t(vv[J], smb + FV_H + vrow + (uint32_t)(J * 32) + toffV);
#pragma unroll
            for (int J = 0; J < 8; J++) {
                mma_bf16(oacc[2 * J + 0], a_h, vv[J][0], vv[J][1]);
                mma_bf16(oacc[2 * J + 1], a_h, vv[J][2], vv[J][3]);
            }
#pragma unroll
            for (int J = 0; J < 8; J++) {
                mma_bf16(oacc[2 * J + 0], a_l, vv[J][0], vv[J][1]);
                mma_bf16(oacc[2 * J + 1], a_l, vv[J][2], vv[J][3]);
            }
#pragma unroll
            for (int J = 0; J < 8; J++)
                ldsm_x4_t(vv[J], smb + FV_L + vrow + (uint32_t)(J * 32) + toffV);
#pragma unroll
            for (int J = 0; J < 8; J++) {
                mma_bf16(oacc[2 * J + 0], a_h, vv[J][0], vv[J][1]);
                mma_bf16(oacc[2 * J + 1], a_h, vv[J][2], vv[J][3]);
            }
        }
        __syncthreads();       // all warps done with V smem
        load_kv(ktn, false);   // prefetch V(kt+1) during next QK
        CP_COMMIT();
    }
    CP_WAIT0();

    // ---- normalize + write O as bf16 hi/lo ----
    const float inv0 = 1.f / l0, inv1 = 1.f / l1;
    const int r0g = qt * 64 + wid * 16 + g;
#pragma unroll
    for (int f = 0; f < 16; f++) {
        int col = 8 * f + 2 * cq;
        size_t b0a = (rowbase + r0g) * DIM + coloff + col;
        size_t b1a = (rowbase + r0g + 8) * DIM + coloff + col;
        uint32_t h0, lo0, h1, lo1;
        split2pack(oacc[f][0] * inv0, oacc[f][1] * inv0, h0, lo0);
        split2pack(oacc[f][2] * inv1, oacc[f][3] * inv1, h1, lo1);
        *reinterpret_cast<uint32_t*>(&Ohi[b0a]) = h0;
        *reinterpret_cast<uint32_t*>(&Olo[b0a]) = lo0;
        *reinterpret_cast<uint32_t*>(&Ohi[b1a]) = h1;
        *reinterpret_cast<uint32_t*>(&Olo[b1a]) = lo1;
    }
}

// ============================================================================
// Launch
// ============================================================================
extern "C" void kernel_launch(void* const* d_in, const int* in_sizes, int n_in,
                              void* d_out, int out_size)
{
    (void)in_sizes; (void)n_in; (void)out_size;
    const float* x  = (const float*)d_in[0];
    const float* Wq = (const float*)d_in[1];
    const float* Wk = (const float*)d_in[2];
    const float* Wv = (const float*)d_in[3];
    const float* Wo = (const float*)d_in[4];
    float* out = (float*)d_out;

    float *Qp, *Kp;
    __nv_bfloat16 *ah, *al, *bh, *bl, *qh, *ql, *kh, *kl, *vh, *vl;
    cudaGetSymbolAddress((void**)&Qp, g_Q);
    cudaGetSymbolAddress((void**)&Kp, g_K);
    cudaGetSymbolAddress((void**)&ah, g_ah);
    cudaGetSymbolAddress((void**)&al, g_al);
    cudaGetSymbolAddress((void**)&bh, g_bh);
    cudaGetSymbolAddress((void**)&bl, g_bl);
    cudaGetSymbolAddress((void**)&qh, g_qh);
    cudaGetSymbolAddress((void**)&ql, g_ql);
    cudaGetSymbolAddress((void**)&kh, g_kh);
    cudaGetSymbolAddress((void**)&kl, g_kl);
    cudaGetSymbolAddress((void**)&vh, g_vh);
    cudaGetSymbolAddress((void**)&vl, g_vl);

    cudaFuncSetAttribute(gemm_mma, cudaFuncAttributeMaxDynamicSharedMemorySize,
                         G_SMEM);
    cudaFuncSetAttribute(flash_mma, cudaFuncAttributeMaxDynamicSharedMemorySize,
                         F_SMEM);

    const int nx4 = (int)(ELEMS / 4);
    const int nw4 = (int)(WSZ / 4);

    init_invfreq<<<1, 64>>>();

    // All weight splits in one launch; x split
    split_w4<<<dim3(nw4 / 256, 4), 256>>>(Wq, Wk, Wv, Wo, bh, bl);
    split_bf16<<<(nx4 + 255) / 256, 256>>>(x, ah, al, nx4);

    // Fused QKV projection: z=0 -> Q (fp32), z=1 -> K (fp32), z=2 -> V (bf16)
    gemm_mma<<<dim3(DIM / 128, MTOT / 128, 3), 128, G_SMEM>>>(
        ah, al, bh, bl, Qp, Kp, vh, vl, MTOT, DIM, DIM);

    // RoPE + split for Q and K in one launch
    int rope_blocks = (BATCH * SEQ * NHEAD * 64) / 256;   // 16384
    rope_split<<<dim3(rope_blocks, 2), 256>>>(Qp, Kp, qh, ql, kh, kl);

    // Tensor-core causal flash attention (64-row tiles, 2 CTAs/SM)
    flash_mma<<<dim3(SEQ / 64, NHEAD, BATCH), 128, F_SMEM>>>(qh, ql, kh, kl,
                                                             vh, vl, ah, al);

    // Output projection (weight slice 3); z=0 path writes fp32 to out
    gemm_mma<<<dim3(DIM / 128, MTOT / 128, 1), 128, G_SMEM>>>(
        ah, al, bh + 3 * WSZ, bl + 3 * WSZ, out, nullptr, nullptr, nullptr,
        MTOT, DIM, DIM);
}